// round 4
// baseline (speedup 1.0000x reference)
#include <cuda_runtime.h>
#include <math.h>

// Problem constants (from reference setup_inputs)
#define B 8
#define C 64
#define SPATIAL (48*48*48)        // 110592 floats per (b,c) channel
#define SPATIAL4 (SPATIAL/4)      // 27648 float4 per channel
#define SEGS 4                    // segments per row
#define SEG4 (SPATIAL4/SEGS)      // 6912 float4 per segment
#define NBLK (B*C*SEGS)           // 2048 blocks
#define R 8
#define NEG_SLOPE 0.01f
#define WPAD 65                   // padded transposed weight stride

// Scratch (no cudaMalloc allowed)
__device__ float g_partials[NBLK];
__device__ int   g_idx[B * R];
__device__ int   g_count = 0;     // self-resetting ticket

// ---------------------------------------------------------------------------
// Kernel 1: fused mean + MLP + top-k.
// 2048 blocks compute quarter-row partial sums; the last block to finish
// reduces partials, runs the tiny MLP (weights staged in SMEM, transposed,
// conflict-free) + top-8, then resets the ticket (graph-replay safe).
// ---------------------------------------------------------------------------
__global__ __launch_bounds__(512) void mean_mlp_topk_kernel(
    const float* __restrict__ x,
    const float* __restrict__ w1, const float* __restrict__ b1,
    const float* __restrict__ w2, const float* __restrict__ b2,
    int* __restrict__ idx_out) {

    const int blk = blockIdx.x;           // row*SEGS + seg
    const int row = blk >> 2;
    const int seg = blk & 3;
    const float4* __restrict__ p =
        reinterpret_cast<const float4*>(x + (size_t)row * SPATIAL) + seg * SEG4;

    float ax = 0.f, ay = 0.f, az = 0.f, aw = 0.f;
    // 6912 float4 / 512 threads = 13.5 iterations
    for (int i = threadIdx.x; i < SEG4; i += 512) {
        float4 v = p[i];
        ax += v.x; ay += v.y; az += v.z; aw += v.w;
    }
    float acc = (ax + ay) + (az + aw);

    // warp reduce
    for (int off = 16; off > 0; off >>= 1)
        acc += __shfl_down_sync(0xFFFFFFFFu, acc, off);

    __shared__ float warp_sums[16];
    const int lane = threadIdx.x & 31;
    const int wid  = threadIdx.x >> 5;
    if (lane == 0) warp_sums[wid] = acc;
    __syncthreads();

    __shared__ bool is_last;
    if (threadIdx.x == 0) {
        float s = 0.f;
#pragma unroll
        for (int w = 0; w < 16; w++) s += warp_sums[w];
        g_partials[blk] = s;
        __threadfence();
        int old = atomicAdd(&g_count, 1);
        is_last = (old == NBLK - 1);
    }
    __syncthreads();
    if (!is_last) return;

    // ---------------- last block: reduce partials + MLP + topk ------------
    __shared__ float sm[B * C];          // means
    __shared__ float y1[B * C];
    __shared__ float y2[B * C];
    __shared__ float wT[C * WPAD];       // transposed padded weights (reused)

    const int t = threadIdx.x;           // 0..511

    // Stage w1 transposed: wT[j*WPAD + i] = w1[i*C + j].
    // Global read linear (coalesced); smem store stride WPAD=65 -> no conflicts.
    {
        const float vw = w1[t];                  // t = i*C + j  (first 512)
        wT[(t & 63) * WPAD + (t >> 6)] = vw;
        const float vw2 = w1[t + 512];
        wT[((t + 512) & 63) * WPAD + ((t + 512) >> 6)] = vw2;
        const float vw3 = w1[t + 1024];
        wT[((t + 1024) & 63) * WPAD + ((t + 1024) >> 6)] = vw3;
        const float vw4 = w1[t + 1536];
        wT[((t + 1536) & 63) * WPAD + ((t + 1536) >> 6)] = vw4;
        const float vw5 = w1[t + 2048];
        wT[((t + 2048) & 63) * WPAD + ((t + 2048) >> 6)] = vw5;
        const float vw6 = w1[t + 2560];
        wT[((t + 2560) & 63) * WPAD + ((t + 2560) >> 6)] = vw6;
        const float vw7 = w1[t + 3072];
        wT[((t + 3072) & 63) * WPAD + ((t + 3072) >> 6)] = vw7;
        const float vw8 = w1[t + 3584];
        wT[((t + 3584) & 63) * WPAD + ((t + 3584) >> 6)] = vw8;
    }

    // Reduce partials -> means (512 rows, one per thread)
    {
        float4 ps = reinterpret_cast<const float4*>(g_partials)[t];
        sm[t] = ((ps.x + ps.y) + (ps.z + ps.w)) * (1.0f / (float)SPATIAL);
    }
    __syncthreads();

    // layer 1: y1[b][i] = leaky( sum_j means[b][j] * wT[j][i] + b1[i] )
    {
        const int b = t >> 6, i = t & 63;
        float a = b1[i];
        const float* __restrict__ mrow = sm + b * C;
#pragma unroll 16
        for (int j = 0; j < C; j++) a += mrow[j] * wT[j * WPAD + i];
        y1[t] = (a > 0.0f) ? a : NEG_SLOPE * a;
    }
    __syncthreads();

    // Stage w2 transposed (overwrite wT)
    {
#pragma unroll
        for (int k = 0; k < 8; k++) {
            const int u = t + k * 512;
            wT[(u & 63) * WPAD + (u >> 6)] = w2[u];
        }
    }
    __syncthreads();

    // layer 2: y2[b][i] = sigmoid( sum_j y1[b][j] * wT[j][i] + b2[i] )
    {
        const int b = t >> 6, i = t & 63;
        float a = b2[i];
        const float* __restrict__ y1row = y1 + b * C;
#pragma unroll 16
        for (int j = 0; j < C; j++) a += y1row[j] * wT[j * WPAD + i];
        y2[t] = 1.0f / (1.0f + expf(-a));
    }
    __syncthreads();

    // top-8 per batch; strict '>' keeps earliest index on ties (jax top_k).
    // No local arrays: scan smem, track used indices in a register bitmask.
    if (t < B) {
        unsigned long long used = 0ULL;
        const float* __restrict__ yb = y2 + t * C;
#pragma unroll
        for (int r = 0; r < R; r++) {
            int   best_j = -1;
            float best_v = -1.0f;     // sigmoid outputs in (0,1)
#pragma unroll
            for (int j = 0; j < C; j++) {
                const bool free = ((used >> j) & 1ULL) == 0ULL;
                const float vj = yb[j];
                if (free && vj > best_v) { best_v = vj; best_j = j; }
            }
            idx_out[t * R + r] = best_j;
            used |= (1ULL << best_j);
        }
    }

    // reset ticket for next graph replay
    if (t == 0) g_count = 0;
}

// ---------------------------------------------------------------------------
// Kernel 2: gather selected channels: out[b][r][:] = x[b][idx[b][r]][:]
// grid = (27, 64); each thread copies 4 float4 (strided).
// ---------------------------------------------------------------------------
__global__ __launch_bounds__(256) void gather_kernel(const float* __restrict__ x,
                                                     const int* __restrict__ idx,
                                                     float* __restrict__ out) {
    const int row = blockIdx.y;          // 0..63 : b*R + r
    const int b   = row >> 3;
    const int ch  = __ldg(idx + row);

    const float4* __restrict__ src =
        reinterpret_cast<const float4*>(x + ((size_t)b * C + ch) * SPATIAL);
    float4* __restrict__ dst =
        reinterpret_cast<float4*>(out + (size_t)row * SPATIAL);

    const int base = blockIdx.x * (256 * 4) + threadIdx.x;
#pragma unroll
    for (int k = 0; k < 4; k++) {
        const int i = base + k * 256;
        dst[i] = src[i];   // 27648 = 27*256*4 exactly: no bounds check
    }
}

// ---------------------------------------------------------------------------
extern "C" void kernel_launch(void* const* d_in, const int* in_sizes, int n_in,
                              void* d_out, int out_size) {
    const float* x  = (const float*)d_in[0];
    const float* w1 = (const float*)d_in[1];
    const float* b1 = (const float*)d_in[2];
    const float* w2 = (const float*)d_in[3];
    const float* b2 = (const float*)d_in[4];
    float* out = (float*)d_out;

    int* idx;
    cudaGetSymbolAddress((void**)&idx, g_idx);

    mean_mlp_topk_kernel<<<NBLK, 512>>>(x, w1, b1, w2, b2, idx);
    dim3 grid(SPATIAL4 / (256 * 4), B * R);   // (27, 64)
    gather_kernel<<<grid, 256>>>(x, idx, out);
}

// round 5
// speedup vs baseline: 2.3082x; 2.3082x over previous
#include <cuda_runtime.h>
#include <math.h>

// Problem constants (from reference setup_inputs)
#define B 8
#define C 64
#define SPATIAL (48*48*48)        // 110592 floats per (b,c) channel
#define SPATIAL4 (SPATIAL/4)      // 27648 float4 per channel
#define SEGS 2                    // half-row segments
#define SEG4 (SPATIAL4/SEGS)      // 13824 float4 per segment
#define NBLK1 (B*C*SEGS)          // 1024 reduction blocks
#define R 8
#define NEG_SLOPE 0.01f
#define WPAD 65                   // padded transposed weight stride

// Scratch (no cudaMalloc allowed)
__device__ float g_partials[NBLK1];

// ---------------------------------------------------------------------------
// Kernel 1: half-row partial sums. 1024 blocks x 256 threads (fills the chip
// better than 512 blocks), float4 loads, 4 independent accumulators.
// ---------------------------------------------------------------------------
__global__ __launch_bounds__(256) void mean_partial_kernel(
    const float* __restrict__ x, float* __restrict__ partials) {
    const int blk = blockIdx.x;          // row*2 + seg
    const int row = blk >> 1;
    const int seg = blk & 1;
    const float4* __restrict__ p =
        reinterpret_cast<const float4*>(x + (size_t)row * SPATIAL) + seg * SEG4;

    float ax = 0.f, ay = 0.f, az = 0.f, aw = 0.f;
    // 13824 / 256 = 54 iterations; unroll 6 for deep LDG batching
#pragma unroll 6
    for (int i = threadIdx.x; i < SEG4; i += 256) {
        float4 v = p[i];
        ax += v.x; ay += v.y; az += v.z; aw += v.w;
    }
    float acc = (ax + ay) + (az + aw);

    for (int off = 16; off > 0; off >>= 1)
        acc += __shfl_down_sync(0xFFFFFFFFu, acc, off);

    __shared__ float warp_sums[8];
    const int lane = threadIdx.x & 31;
    const int wid  = threadIdx.x >> 5;
    if (lane == 0) warp_sums[wid] = acc;
    __syncthreads();

    if (threadIdx.x == 0) {
        float s = warp_sums[0] + warp_sums[1] + warp_sums[2] + warp_sums[3]
                + warp_sums[4] + warp_sums[5] + warp_sums[6] + warp_sums[7];
        partials[blk] = s;
    }
}

// ---------------------------------------------------------------------------
// Kernel 2: gather fused with a redundant per-block MLP + top-k.
// Every block deterministically recomputes the 64->64->64 MLP for its batch
// and selects its own rank-r channel, then copies that channel. No sync
// between blocks; identical FP sequence in every block => deterministic.
// grid = (27, 64), 256 threads; each thread copies 4 float4.
// ---------------------------------------------------------------------------
__global__ __launch_bounds__(256) void gather_mlp_kernel(
    const float* __restrict__ x,
    const float* __restrict__ w1, const float* __restrict__ b1,
    const float* __restrict__ w2, const float* __restrict__ b2,
    const float* __restrict__ partials,
    float* __restrict__ out) {

    __shared__ float wT[C * WPAD];   // transposed padded weights (reused)
    __shared__ float mb[C];          // means for this batch
    __shared__ float y1[C];
    __shared__ float y2[C];
    __shared__ int   ch_s;

    const int row = blockIdx.y;      // 0..63 : b*R + r
    const int b   = row >> 3;
    const int r   = row & 7;
    const int t   = threadIdx.x;

    // Stage w1 transposed: wT[j*WPAD+i] = w1[i*C+j]. Coalesced global reads,
    // conflict-free smem stores (stride 65).
#pragma unroll
    for (int k = 0; k < 16; k++) {
        const int u = t + k * 256;
        wT[(u & 63) * WPAD + (u >> 6)] = w1[u];
    }
    if (t < C) {
        const int p0 = 2 * (b * C + t);
        mb[t] = (partials[p0] + partials[p0 + 1]) * (1.0f / (float)SPATIAL);
    }
    __syncthreads();

    // layer 1: y1[i] = leaky( sum_j mb[j] * wT[j][i] + b1[i] )
    if (t < C) {
        float a = b1[t];
#pragma unroll 16
        for (int j = 0; j < C; j++) a += mb[j] * wT[j * WPAD + t];
        y1[t] = (a > 0.0f) ? a : NEG_SLOPE * a;
    }
    __syncthreads();

    // Stage w2 transposed (overwrite wT)
#pragma unroll
    for (int k = 0; k < 16; k++) {
        const int u = t + k * 256;
        wT[(u & 63) * WPAD + (u >> 6)] = w2[u];
    }
    __syncthreads();

    // layer 2: y2[i] = sigmoid( sum_j y1[j] * wT[j][i] + b2[i] )
    if (t < C) {
        float a = b2[t];
#pragma unroll 16
        for (int j = 0; j < C; j++) a += y1[j] * wT[j * WPAD + t];
        y2[t] = 1.0f / (1.0f + expf(-a));
    }
    __syncthreads();

    // Warp 0: r+1 rounds of warp-parallel argmax over 64 channels.
    // Tie-break: strictly-greater wins; ties keep the smaller index (jax top_k).
    if (t < 32) {
        float v0 = y2[t];
        float v1 = y2[t + 32];
        int sel = 0;
        for (int round = 0; round <= r; round++) {
            float bv; int bj;
            if (v0 >= v1) { bv = v0; bj = t; }        // tie -> smaller index
            else          { bv = v1; bj = t + 32; }
#pragma unroll
            for (int off = 16; off > 0; off >>= 1) {
                const float ov = __shfl_down_sync(0xFFFFFFFFu, bv, off);
                const int   oj = __shfl_down_sync(0xFFFFFFFFu, bj, off);
                if (ov > bv || (ov == bv && oj < bj)) { bv = ov; bj = oj; }
            }
            bj = __shfl_sync(0xFFFFFFFFu, bj, 0);
            sel = bj;
            if (bj == t)      v0 = -1.0f;             // sigmoid in (0,1)
            if (bj == t + 32) v1 = -1.0f;
        }
        if (t == 0) ch_s = sel;
    }
    __syncthreads();

    // Copy the selected channel: 4 float4 per thread.
    const int ch = ch_s;
    const float4* __restrict__ src =
        reinterpret_cast<const float4*>(x + ((size_t)b * C + ch) * SPATIAL);
    float4* __restrict__ dst =
        reinterpret_cast<float4*>(out) + (size_t)row * SPATIAL4;

    const int base = blockIdx.x * (256 * 4) + t;
#pragma unroll
    for (int k = 0; k < 4; k++) {
        const int i = base + k * 256;
        dst[i] = src[i];   // 27648 = 27*256*4 exactly: no bounds check
    }
}

// ---------------------------------------------------------------------------
extern "C" void kernel_launch(void* const* d_in, const int* in_sizes, int n_in,
                              void* d_out, int out_size) {
    const float* x  = (const float*)d_in[0];
    const float* w1 = (const float*)d_in[1];
    const float* b1 = (const float*)d_in[2];
    const float* w2 = (const float*)d_in[3];
    const float* b2 = (const float*)d_in[4];
    float* out = (float*)d_out;

    float* partials;
    cudaGetSymbolAddress((void**)&partials, g_partials);

    mean_partial_kernel<<<NBLK1, 256>>>(x, partials);
    dim3 grid(SPATIAL4 / (256 * 4), B * R);   // (27, 64)
    gather_mlp_kernel<<<grid, 256>>>(x, w1, b1, w2, b2, partials, out);
}

// round 6
// speedup vs baseline: 2.4450x; 1.0593x over previous
#include <cuda_runtime.h>
#include <math.h>

// Problem constants (from reference setup_inputs)
#define B 8
#define C 64
#define SPATIAL (48*48*48)        // 110592 floats per (b,c) channel
#define SPATIAL4 (SPATIAL/4)      // 27648 float4 per channel
#define SEGS 4                    // quarter-row segments
#define SEG4 (SPATIAL4/SEGS)      // 6912 float4 per segment
#define NBLK1 (B*C*SEGS)          // 2048 reduction blocks
#define R 8
#define NEG_SLOPE 0.01f

// gather kernel geometry
#define GT 512                    // threads
#define GK 6                      // float4 per thread
#define GBX (SPATIAL4/(GT*GK))    // 9 blocks along the row

// Scratch (no cudaMalloc allowed)
__device__ float g_partials[NBLK1];

// ---------------------------------------------------------------------------
// Kernel 1: quarter-row partial sums. 2048 blocks x 256 threads.
// ---------------------------------------------------------------------------
__global__ __launch_bounds__(256) void mean_partial_kernel(
    const float* __restrict__ x, float* __restrict__ partials) {
    const int blk = blockIdx.x;          // row*4 + seg
    const int row = blk >> 2;
    const int seg = blk & 3;
    const float4* __restrict__ p =
        reinterpret_cast<const float4*>(x + (size_t)row * SPATIAL) + seg * SEG4;

    float ax = 0.f, ay = 0.f, az = 0.f, aw = 0.f;
    // 6912 / 256 = 27 iterations
#pragma unroll 9
    for (int i = threadIdx.x; i < SEG4; i += 256) {
        float4 v = p[i];
        ax += v.x; ay += v.y; az += v.z; aw += v.w;
    }
    float acc = (ax + ay) + (az + aw);

    for (int off = 16; off > 0; off >>= 1)
        acc += __shfl_down_sync(0xFFFFFFFFu, acc, off);

    __shared__ float warp_sums[8];
    const int lane = threadIdx.x & 31;
    const int wid  = threadIdx.x >> 5;
    if (lane == 0) warp_sums[wid] = acc;
    __syncthreads();

    if (threadIdx.x == 0) {
        float s = warp_sums[0] + warp_sums[1] + warp_sums[2] + warp_sums[3]
                + warp_sums[4] + warp_sums[5] + warp_sums[6] + warp_sums[7];
        partials[blk] = s;
    }
}

// ---------------------------------------------------------------------------
// Kernel 2: gather fused with a redundant per-block warp-cooperative MLP.
// Warp w computes output channels 4w..4w+3 of each layer; lane l reads
// w[i*64+l] / w[i*64+32+l] straight from global (coalesced), 2 FMAs +
// shuffle reduce. No weight staging, no transpose. Every block runs the
// identical FP sequence => deterministic. grid = (9, 64), 512 threads,
// 6 float4 copied per thread.
// ---------------------------------------------------------------------------
__global__ __launch_bounds__(GT) void gather_mlp_kernel(
    const float* __restrict__ x,
    const float* __restrict__ w1, const float* __restrict__ b1,
    const float* __restrict__ w2, const float* __restrict__ b2,
    const float* __restrict__ partials,
    float* __restrict__ out) {

    __shared__ float mb[C];          // means for this batch
    __shared__ float y1[C];
    __shared__ float y2[C];
    __shared__ int   ch_s;

    const int row = blockIdx.y;      // 0..63 : b*R + r
    const int b   = row >> 3;
    const int r   = row & 7;
    const int t   = threadIdx.x;
    const int lane = t & 31;
    const int wrp  = t >> 5;         // 0..15

    // means: thread t<64 reduces the 4 quarter-row partials of channel t
    if (t < C) {
        float4 ps = reinterpret_cast<const float4*>(partials)[b * C + t];
        mb[t] = ((ps.x + ps.y) + (ps.z + ps.w)) * (1.0f / (float)SPATIAL);
    }
    __syncthreads();

    // layer 1: warp w -> channels 4w..4w+3
    {
        const float m0 = mb[lane];
        const float m1 = mb[lane + 32];
#pragma unroll
        for (int c = 0; c < 4; c++) {
            const int i = 4 * wrp + c;
            const float* __restrict__ wr = w1 + i * C;
            float a = m0 * wr[lane] + m1 * wr[lane + 32];
#pragma unroll
            for (int off = 16; off > 0; off >>= 1)
                a += __shfl_down_sync(0xFFFFFFFFu, a, off);
            if (lane == 0) {
                a += b1[i];
                y1[i] = (a > 0.0f) ? a : NEG_SLOPE * a;
            }
        }
    }
    __syncthreads();

    // layer 2: same pattern with w2, sigmoid
    {
        const float h0 = y1[lane];
        const float h1 = y1[lane + 32];
#pragma unroll
        for (int c = 0; c < 4; c++) {
            const int i = 4 * wrp + c;
            const float* __restrict__ wr = w2 + i * C;
            float a = h0 * wr[lane] + h1 * wr[lane + 32];
#pragma unroll
            for (int off = 16; off > 0; off >>= 1)
                a += __shfl_down_sync(0xFFFFFFFFu, a, off);
            if (lane == 0) {
                a += b2[i];
                y2[i] = 1.0f / (1.0f + expf(-a));
            }
        }
    }
    __syncthreads();

    // Warp 0: r+1 rounds of warp-parallel argmax over 64 channels.
    // Strictly-greater wins; ties keep the smaller index (jax top_k).
    if (t < 32) {
        float v0 = y2[t];
        float v1 = y2[t + 32];
        int sel = 0;
        for (int round = 0; round <= r; round++) {
            float bv; int bj;
            if (v0 >= v1) { bv = v0; bj = t; }        // tie -> smaller index
            else          { bv = v1; bj = t + 32; }
#pragma unroll
            for (int off = 16; off > 0; off >>= 1) {
                const float ov = __shfl_down_sync(0xFFFFFFFFu, bv, off);
                const int   oj = __shfl_down_sync(0xFFFFFFFFu, bj, off);
                if (ov > bv || (ov == bv && oj < bj)) { bv = ov; bj = oj; }
            }
            bj = __shfl_sync(0xFFFFFFFFu, bj, 0);
            sel = bj;
            if (bj == t)      v0 = -1.0f;             // sigmoid in (0,1)
            if (bj == t + 32) v1 = -1.0f;
        }
        if (t == 0) ch_s = sel;
    }
    __syncthreads();

    // Copy the selected channel: 6 float4 per thread, coalesced.
    const int ch = ch_s;
    const float4* __restrict__ src =
        reinterpret_cast<const float4*>(x + ((size_t)b * C + ch) * SPATIAL);
    float4* __restrict__ dst =
        reinterpret_cast<float4*>(out) + (size_t)row * SPATIAL4;

#pragma unroll
    for (int k = 0; k < GK; k++) {
        const int i = (blockIdx.x * GK + k) * GT + t;  // covers 0..27647 exactly
        dst[i] = src[i];
    }
}

// ---------------------------------------------------------------------------
extern "C" void kernel_launch(void* const* d_in, const int* in_sizes, int n_in,
                              void* d_out, int out_size) {
    const float* x  = (const float*)d_in[0];
    const float* w1 = (const float*)d_in[1];
    const float* b1 = (const float*)d_in[2];
    const float* w2 = (const float*)d_in[3];
    const float* b2 = (const float*)d_in[4];
    float* out = (float*)d_out;

    float* partials;
    cudaGetSymbolAddress((void**)&partials, g_partials);

    mean_partial_kernel<<<NBLK1, 256>>>(x, partials);
    dim3 grid(GBX, B * R);   // (9, 64)
    gather_mlp_kernel<<<grid, GT>>>(x, w1, b1, w2, b2, partials, out);
}